// round 1
// baseline (speedup 1.0000x reference)
#include <cuda_runtime.h>
#include <math.h>

// Problem dims (fixed): B=4, N=32, T=512, D_MODEL=512, HIDDEN=512, D_K=32
#define R_TOT 65536          // B*N*T rows
#define DM    512
#define H3    1536
#define PI_D  3.14159265358979323846

// ---------------- scratch (static __device__, allocation-free) ----------------
__device__ float g_Q[R_TOT * DM];     // q rows (b,n,t) x h
__device__ float g_K[R_TOT * DM];
__device__ float g_V[R_TOT * DM];
__device__ float g_Hk[R_TOT * DM];    // Mi @ k per row
__device__ float g_T1[R_TOT * DM];    // mlp hidden
__device__ float g_T2[R_TOT * DM];    // mlp out + residual
__device__ float g_MiT[DM * DM];      // B matrix for Hk GEMM: MiT[n*512+m] = Mi[m,n]
__device__ float g_coh[R_TOT];        // scaled coherence
__device__ float g_attnc[R_TOT];      // trace * softmax weight
__device__ float g_trace;

// ---------------- init: Mi matrix + zero trace ----------------
__global__ void init_mi_kernel() {
    int n = blockIdx.x;
    for (int m = threadIdx.x; m < DM; m += blockDim.x) {
        int d = m - n;
        float v = 0.0f;
        if (d & 1) v = (float)(-1.0 / tan(PI_D * (double)d / 512.0));
        g_MiT[n * DM + m] = v;
    }
    if (blockIdx.x == 0 && threadIdx.x == 0) g_trace = 0.0f;
}

// ---------------- trace(softmax(var_attn)) ----------------
__global__ void trace_kernel(const float* __restrict__ va) {
    __shared__ float red[128];
    int i = blockIdx.x;
    const float* row = va + (size_t)i * DM;
    int t = threadIdx.x;
    float mx = -1e30f;
    for (int j = t; j < DM; j += 128) mx = fmaxf(mx, row[j]);
    red[t] = mx; __syncthreads();
    for (int s = 64; s > 0; s >>= 1) {
        if (t < s) red[t] = fmaxf(red[t], red[t + s]);
        __syncthreads();
    }
    mx = red[0]; __syncthreads();
    float sum = 0.0f;
    for (int j = t; j < DM; j += 128) sum += expf(row[j] - mx);
    red[t] = sum; __syncthreads();
    for (int s = 64; s > 0; s >>= 1) {
        if (t < s) red[t] += red[t + s];
        __syncthreads();
    }
    if (t == 0) atomicAdd(&g_trace, expf(row[i] - mx) / red[0]);
}

// ---------------- generic tiled SIMT GEMM, 128x128x8, 8x8 per thread ----------------
// MODE 0: C = coeffs @ proj_w + proj_b, de-interleaved into g_Q/g_K/g_V   (N=1536)
// MODE 1: g_Hk = g_K @ g_MiT                                              (N=512)
// MODE 2: g_T1 = gelu((attnc[r]*g_V) @ mlp1_w + b1)
// MODE 3: g_T2 = g_T1 @ mlp2_w + b2 + attnc[r]*g_V[r,:]
// MODE 4: d_out = g_T2 @ out_w + out_b
#define BM 128
#define BN 128
#define BK 8

template <int MODE>
__global__ __launch_bounds__(256, 2)
void gemm_kernel(const float* __restrict__ Aext, const float* __restrict__ Bext,
                 const float* __restrict__ bias, float* __restrict__ Cext,
                 int N, int K) {
    const float* A;
    const float* Bm;
    if (MODE == 0)      { A = Aext; Bm = Bext; }
    else if (MODE == 1) { A = g_K;  Bm = g_MiT; }
    else if (MODE == 2) { A = g_V;  Bm = Bext; }
    else if (MODE == 3) { A = g_T1; Bm = Bext; }
    else                { A = g_T2; Bm = Bext; }

    __shared__ float As[BK][BM + 4];
    __shared__ float Bs[BK][BN + 4];

    int tid = threadIdx.x;                 // 0..255
    int tx = tid & 15, ty = tid >> 4;      // 16x16 thread grid
    int bm = blockIdx.y * BM, bn = blockIdx.x * BN;

    int a_row  = tid >> 1;                 // 0..127
    int a_col4 = (tid & 1) * 4;            // 0 or 4
    int b_row  = tid >> 5;                 // 0..7
    int b_col4 = (tid & 31) * 4;           // 0..124

    float rsA = 1.0f;
    if (MODE == 2) rsA = g_attnc[bm + a_row];

    const float* Aptr = A + (size_t)(bm + a_row) * K + a_col4;
    const float* Bptr = Bm + (size_t)b_row * N + bn + b_col4;

    float acc[8][8] = {};

    for (int k0 = 0; k0 < K; k0 += BK) {
        float4 av = *(const float4*)(Aptr + k0);
        if (MODE == 2) { av.x *= rsA; av.y *= rsA; av.z *= rsA; av.w *= rsA; }
        As[a_col4 + 0][a_row] = av.x;
        As[a_col4 + 1][a_row] = av.y;
        As[a_col4 + 2][a_row] = av.z;
        As[a_col4 + 3][a_row] = av.w;
        *(float4*)&Bs[b_row][b_col4] = *(const float4*)(Bptr + (size_t)k0 * N);
        __syncthreads();

        #pragma unroll
        for (int k = 0; k < BK; k++) {
            float4 a0 = *(const float4*)&As[k][ty * 8];
            float4 a1 = *(const float4*)&As[k][ty * 8 + 4];
            float4 b0 = *(const float4*)&Bs[k][tx * 8];
            float4 b1 = *(const float4*)&Bs[k][tx * 8 + 4];
            float ar[8] = {a0.x, a0.y, a0.z, a0.w, a1.x, a1.y, a1.z, a1.w};
            float br[8] = {b0.x, b0.y, b0.z, b0.w, b1.x, b1.y, b1.z, b1.w};
            #pragma unroll
            for (int i = 0; i < 8; i++)
                #pragma unroll
                for (int j = 0; j < 8; j++)
                    acc[i][j] += ar[i] * br[j];
        }
        __syncthreads();
    }

    #pragma unroll
    for (int i = 0; i < 8; i++) {
        int m = bm + ty * 8 + i;
        #pragma unroll
        for (int j = 0; j < 8; j++) {
            int n = bn + tx * 8 + j;
            float v = acc[i][j];
            if (MODE == 0) {
                v += bias[n];
                int which = n % 3, col = n / 3;
                float* dst = (which == 0) ? g_Q : (which == 1) ? g_K : g_V;
                dst[(size_t)m * DM + col] = v;
            } else if (MODE == 1) {
                g_Hk[(size_t)m * DM + n] = v;
            } else if (MODE == 2) {
                v += bias[n];
                v = 0.5f * v * (1.0f + erff(v * 0.7071067811865476f));
                g_T1[(size_t)m * DM + n] = v;
            } else if (MODE == 3) {
                v += bias[n] + g_attnc[m] * g_V[(size_t)m * DM + n];
                g_T2[(size_t)m * DM + n] = v;
            } else {
                v += bias[n];
                Cext[(size_t)m * DM + n] = v;
            }
        }
    }
}

// ---------------- per-row coherence via closed-form spectral identities ----------------
__global__ void coherence_kernel() {
    int r = blockIdx.x;
    const float* q  = g_Q  + (size_t)r * DM;
    const float* k  = g_K  + (size_t)r * DM;
    const float* hk = g_Hk + (size_t)r * DM;

    float qk = 0, qq = 0, kk = 0, se_q = 0, so_q = 0, se_k = 0, so_k = 0, qh = 0;
    for (int h = threadIdx.x; h < DM; h += 128) {
        float qv = q[h], kv = k[h];
        qk += qv * kv; qq += qv * qv; kk += kv * kv; qh += qv * hk[h];
        if (h & 1) { so_q += qv; so_k += kv; }
        else       { se_q += qv; se_k += kv; }
    }

    __shared__ float sred[8][4];
    float vals[8] = {qk, qq, kk, se_q, so_q, se_k, so_k, qh};
    int lane = threadIdx.x & 31, wid = threadIdx.x >> 5;
    #pragma unroll
    for (int i = 0; i < 8; i++) {
        float v = vals[i];
        #pragma unroll
        for (int o = 16; o > 0; o >>= 1) v += __shfl_down_sync(0xffffffffu, v, o);
        if (lane == 0) sred[i][wid] = v;
    }
    __syncthreads();
    if (threadIdx.x == 0) {
        float s[8];
        #pragma unroll
        for (int i = 0; i < 8; i++) s[i] = sred[i][0] + sred[i][1] + sred[i][2] + sred[i][3];
        // Re sum_f Qf conj(Kf) = 256*(q.k) + Se(q)Se(k) + So(q)So(k)
        float a   = 256.0f * s[0] + s[3] * s[5] + s[4] * s[6];
        float b   = s[7];                                   // Im part via Mi GEMM
        float pxx = 256.0f * s[1] + s[3] * s[3] + s[4] * s[4];
        float pyy = 256.0f * s[2] + s[5] * s[5] + s[6] * s[6];
        // coherence = |Pxy|^2 / max(|Pxx||Pyy|, 1e-6) with P = S/257
        float coh = (a * a + b * b) / fmaxf(pxx * pyy, 66049.0f * 1e-6f);
        g_coh[r] = coh * 5.656854249492381f;                // pre-mult by sqrt(D_K)
    }
}

// ---------------- softmax over t per (b,n), fold in trace scalar ----------------
__global__ void softmax_kernel() {
    int g = blockIdx.x;                     // 0..127 groups of T=512
    const float* x = g_coh + (size_t)g * 512;
    __shared__ float red[512];
    int t = threadIdx.x;
    float v = x[t];
    red[t] = v; __syncthreads();
    for (int s = 256; s > 0; s >>= 1) {
        if (t < s) red[t] = fmaxf(red[t], red[t + s]);
        __syncthreads();
    }
    float mx = red[0]; __syncthreads();
    float e = expf(v - mx);
    red[t] = e; __syncthreads();
    for (int s = 256; s > 0; s >>= 1) {
        if (t < s) red[t] += red[t + s];
        __syncthreads();
    }
    g_attnc[(size_t)g * 512 + t] = e * (g_trace / red[0]);
}

// ---------------- launch ----------------
extern "C" void kernel_launch(void* const* d_in, const int* in_sizes, int n_in,
                              void* d_out, int out_size) {
    const float* coeffs   = (const float*)d_in[0];
    const float* proj_w   = (const float*)d_in[1];
    const float* proj_b   = (const float*)d_in[2];
    const float* var_attn = (const float*)d_in[3];
    const float* mlp1_w   = (const float*)d_in[4];
    const float* mlp1_b   = (const float*)d_in[5];
    const float* mlp2_w   = (const float*)d_in[6];
    const float* mlp2_b   = (const float*)d_in[7];
    const float* out_w    = (const float*)d_in[8];
    const float* out_b    = (const float*)d_in[9];
    float* out = (float*)d_out;

    (void)in_sizes; (void)n_in; (void)out_size;

    init_mi_kernel<<<512, 256>>>();
    trace_kernel<<<512, 128>>>(var_attn);

    dim3 blk(256);
    // QKV projection: [65536,512] @ [512,1536]
    gemm_kernel<0><<<dim3(H3 / BN, R_TOT / BM), blk>>>(coeffs, proj_w, proj_b, nullptr, H3, DM);
    // Hk = K @ MiT: [65536,512] @ [512,512]
    gemm_kernel<1><<<dim3(DM / BN, R_TOT / BM), blk>>>(nullptr, nullptr, nullptr, nullptr, DM, DM);
    // coherence + softmax
    coherence_kernel<<<R_TOT, 128>>>();
    softmax_kernel<<<128, 512>>>();
    // MLP chain
    gemm_kernel<2><<<dim3(DM / BN, R_TOT / BM), blk>>>(nullptr, mlp1_w, mlp1_b, nullptr, DM, DM);
    gemm_kernel<3><<<dim3(DM / BN, R_TOT / BM), blk>>>(nullptr, mlp2_w, mlp2_b, nullptr, DM, DM);
    gemm_kernel<4><<<dim3(DM / BN, R_TOT / BM), blk>>>(nullptr, out_w, out_b, out, DM, DM);
}

// round 7
// speedup vs baseline: 1.6255x; 1.6255x over previous
#include <cuda_runtime.h>
#include <cuda_bf16.h>
#include <mma.h>
#include <math.h>
#include <stdint.h>

using namespace nvcuda;

// Problem dims (fixed): B=4, N=32, T=512 -> rows=65536; D_MODEL=HIDDEN=512
#define R_TOT 65536
#define DM    512
#define PI_D  3.14159265358979323846

// B-operand scratch offsets in ELEMENTS (bf16 [N,K] layouts, pre-transposed + split)
#define PROJ_OFF 0           // 1536 x 512 (QKV, n permuted: n' = (n%3)*512 + n/3)
#define MI_OFF   786432      // 512 x 512  circulant imag matrix
#define M1_OFF   1048576
#define M2_OFF   1310720
#define OW_OFF   1572864
#define BTOT     1835008

// ---------------- device scratch (allocation-free) ----------------
__device__ __align__(16) float g_Q [R_TOT * DM];
__device__ __align__(16) float g_K [R_TOT * DM];
__device__ __align__(16) float g_V [R_TOT * DM];
__device__ __align__(16) float g_Hk[R_TOT * DM];
__device__ __align__(16) float g_T1[R_TOT * DM];
__device__ __align__(16) float g_T2[R_TOT * DM];
__device__ __align__(16) __nv_bfloat16 g_Bhi[BTOT];
__device__ __align__(16) __nv_bfloat16 g_Blo[BTOT];
__device__ __align__(16) float g_pbias[1536];
__device__ float g_coh[R_TOT];
__device__ float g_attnc[R_TOT];
__device__ float g_trace;

// ---------------- helpers ----------------
__device__ __forceinline__ void split_bf16(float x, unsigned short& h, unsigned short& l) {
    __nv_bfloat16 hb = __float2bfloat16(x);
    __nv_bfloat16 lb = __float2bfloat16(x - __bfloat162float(hb));
    h = __bfloat16_as_ushort(hb);
    l = __bfloat16_as_ushort(lb);
}

// ---------------- prep kernels ----------------
__global__ void prep_proj(const float* __restrict__ w, const float* __restrict__ b) {
    int n_old = blockIdx.x;                              // 0..1535
    int n_new = (n_old % 3) * 512 + n_old / 3;
    for (int k = threadIdx.x; k < 512; k += blockDim.x) {
        float x = w[(size_t)k * 1536 + n_old];
        unsigned short h, l; split_bf16(x, h, l);
        g_Bhi[PROJ_OFF + (size_t)n_new * 512 + k] = __ushort_as_bfloat16(h);
        g_Blo[PROJ_OFF + (size_t)n_new * 512 + k] = __ushort_as_bfloat16(l);
    }
    if (threadIdx.x == 0) g_pbias[n_new] = b[n_old];
}
__global__ void prep_w512(const float* __restrict__ w, int off) {
    int n = blockIdx.x;
    for (int k = threadIdx.x; k < 512; k += blockDim.x) {
        float x = w[(size_t)k * 512 + n];
        unsigned short h, l; split_bf16(x, h, l);
        g_Bhi[off + (size_t)n * 512 + k] = __ushort_as_bfloat16(h);
        g_Blo[off + (size_t)n * 512 + k] = __ushort_as_bfloat16(l);
    }
}
__global__ void prep_mi() {
    int m = blockIdx.x;
    for (int k = threadIdx.x; k < 512; k += blockDim.x) {
        int d = m - k;
        float f = 0.0f;
        if (d & 1) f = (float)(-1.0 / tan(PI_D * (double)d / 512.0));
        unsigned short h, l; split_bf16(f, h, l);
        g_Bhi[MI_OFF + (size_t)m * 512 + k] = __ushort_as_bfloat16(h);
        g_Blo[MI_OFF + (size_t)m * 512 + k] = __ushort_as_bfloat16(l);
    }
    if (blockIdx.x == 0 && threadIdx.x == 0) g_trace = 0.0f;
}
__global__ void trace_kernel(const float* __restrict__ va) {
    __shared__ float red[128];
    int i = blockIdx.x;
    const float* row = va + (size_t)i * DM;
    int t = threadIdx.x;
    float mx = -1e30f;
    for (int j = t; j < DM; j += 128) mx = fmaxf(mx, row[j]);
    red[t] = mx; __syncthreads();
    for (int s = 64; s > 0; s >>= 1) { if (t < s) red[t] = fmaxf(red[t], red[t + s]); __syncthreads(); }
    mx = red[0]; __syncthreads();
    float sum = 0.0f;
    for (int j = t; j < DM; j += 128) sum += expf(row[j] - mx);
    red[t] = sum; __syncthreads();
    for (int s = 64; s > 0; s >>= 1) { if (t < s) red[t] += red[t + s]; __syncthreads(); }
    if (t == 0) atomicAdd(&g_trace, expf(row[i] - mx) / red[0]);
}

// ---------------- WMMA GEMM: C[65536 x N] = A[65536 x 512] @ B^T ----------------
// MODE 0: A=coeffs, B=proj (N=1536, permuted) -> g_Q/g_K/g_V (+pbias)
// MODE 1: A=g_K, B=Mi                          -> g_Hk
// MODE 2: A=attnc*g_V, B=mlp1  -> gelu         -> g_T1 (+bias)
// MODE 3: A=g_T1, B=mlp2  -> +bias+attnc*V     -> g_T2
// MODE 4: A=g_T2, B=out_w -> +bias             -> d_out
#define LDSS 40      // SMEM row stride in bf16 elements (mult of 8; frag ptrs 32B-aligned)
#define AH_OFF 0
#define AL_OFF 5120
#define BH_OFF 10240
#define BL_OFF 15360

template <int MODE>
__global__ __launch_bounds__(256)
void gemm_wmma(const float* __restrict__ Aext, const float* __restrict__ bias,
               float* __restrict__ Cext) {
    __shared__ __align__(32) unsigned char smraw[40960];
    unsigned short* sm = (unsigned short*)smraw;
    __nv_bfloat16* smb = (__nv_bfloat16*)smraw;
    float* sf = (float*)smraw;               // epilogue stage: 128 x 68 floats

    int tid = threadIdx.x, wid = tid >> 5;
    int bn = blockIdx.x * 128, bm = blockIdx.y * 128;

    const float* A;
    size_t boff;
    if (MODE == 0)      { A = Aext;  boff = PROJ_OFF; }
    else if (MODE == 1) { A = g_K;   boff = MI_OFF; }
    else if (MODE == 2) { A = g_V;   boff = M1_OFF; }
    else if (MODE == 3) { A = g_T1;  boff = M2_OFF; }
    else                { A = g_T2;  boff = OW_OFF; }

    // fill coords: each thread owns one row (tid>>1) and half the k-extent of a 32-chunk
    int frow = tid >> 1, kq = (tid & 1) * 16;
    float ascale = 1.0f;
    if (MODE == 2) ascale = g_attnc[bm + frow];

    const float* Arow = A + (size_t)(bm + frow) * 512 + kq;
    // boff is an ELEMENT offset: add it directly (R2-R6 bug: it was scaled by 512)
    const __nv_bfloat16* Bh_row = g_Bhi + boff + (size_t)(bn + frow) * 512 + kq;
    const __nv_bfloat16* Bl_row = g_Blo + boff + (size_t)(bn + frow) * 512 + kq;

    int wm = wid >> 2, wn = wid & 3;        // warp grid 2(m) x 4(n); warp tile 64 x 32

    wmma::fragment<wmma::accumulator, 16, 16, 16, float> cfrag[4][2];
    #pragma unroll
    for (int mi = 0; mi < 4; mi++)
        #pragma unroll
        for (int ni = 0; ni < 2; ni++) wmma::fill_fragment(cfrag[mi][ni], 0.0f);

    // prologue: prefetch chunk 0 into registers
    float4 apre[4];
    uint4  bhpre[2], blpre[2];
    #pragma unroll
    for (int j = 0; j < 4; j++) apre[j] = *(const float4*)(Arow + j * 4);
    #pragma unroll
    for (int j = 0; j < 2; j++) {
        bhpre[j] = *(const uint4*)(Bh_row + j * 8);
        blpre[j] = *(const uint4*)(Bl_row + j * 8);
    }

    for (int c = 0; c < 16; c++) {
        if (c > 0) __syncthreads();          // previous compute done; SMEM reusable

        // ---- store prefetched chunk to SMEM (split A fp32 -> bf16 hi/lo) ----
        int sa = frow * LDSS + kq;
        #pragma unroll
        for (int j = 0; j < 4; j++) {
            float4 v = apre[j];
            if (MODE == 2) { v.x *= ascale; v.y *= ascale; v.z *= ascale; v.w *= ascale; }
            unsigned short h0, h1, h2, h3, l0, l1, l2, l3;
            split_bf16(v.x, h0, l0); split_bf16(v.y, h1, l1);
            split_bf16(v.z, h2, l2); split_bf16(v.w, h3, l3);
            *(uint2*)&sm[AH_OFF + sa + j * 4] =
                make_uint2(((uint32_t)h1 << 16) | h0, ((uint32_t)h3 << 16) | h2);
            *(uint2*)&sm[AL_OFF + sa + j * 4] =
                make_uint2(((uint32_t)l1 << 16) | l0, ((uint32_t)l3 << 16) | l2);
        }
        #pragma unroll
        for (int j = 0; j < 2; j++) {
            *(uint4*)&sm[BH_OFF + sa + j * 8] = bhpre[j];
            *(uint4*)&sm[BL_OFF + sa + j * 8] = blpre[j];
        }

        // ---- prefetch next chunk (overlaps with compute below) ----
        if (c < 15) {
            int ko = (c + 1) * 32;
            #pragma unroll
            for (int j = 0; j < 4; j++) apre[j] = *(const float4*)(Arow + ko + j * 4);
            #pragma unroll
            for (int j = 0; j < 2; j++) {
                bhpre[j] = *(const uint4*)(Bh_row + ko + j * 8);
                blpre[j] = *(const uint4*)(Bl_row + ko + j * 8);
            }
        }
        __syncthreads();

        // ---- compute: 2 ksteps x (4m x 2n x 3 split-products) via WMMA ----
        #pragma unroll
        for (int ks = 0; ks < 2; ks++) {
            int kb = ks * 16;
            wmma::fragment<wmma::matrix_b, 16, 16, 16, __nv_bfloat16, wmma::col_major> bfh[2], bfl[2];
            #pragma unroll
            for (int ni = 0; ni < 2; ni++) {
                int rb = (wn * 32 + ni * 16) * LDSS + kb;
                wmma::load_matrix_sync(bfh[ni], smb + BH_OFF + rb, LDSS);
                wmma::load_matrix_sync(bfl[ni], smb + BL_OFF + rb, LDSS);
            }
            #pragma unroll
            for (int mi = 0; mi < 4; mi++) {
                int ra = (wm * 64 + mi * 16) * LDSS + kb;
                wmma::fragment<wmma::matrix_a, 16, 16, 16, __nv_bfloat16, wmma::row_major> afh, afl;
                wmma::load_matrix_sync(afh, smb + AH_OFF + ra, LDSS);
                wmma::load_matrix_sync(afl, smb + AL_OFF + ra, LDSS);
                #pragma unroll
                for (int ni = 0; ni < 2; ni++) {
                    wmma::mma_sync(cfrag[mi][ni], afh, bfh[ni], cfrag[mi][ni]);
                    wmma::mma_sync(cfrag[mi][ni], afh, bfl[ni], cfrag[mi][ni]);
                    wmma::mma_sync(cfrag[mi][ni], afl, bfh[ni], cfrag[mi][ni]);
                }
            }
        }
    }

    // ---- epilogue: C frags -> SMEM float stage (2 passes of 64 cols) -> fused STG ----
    for (int h = 0; h < 2; h++) {
        __syncthreads();                      // SMEM free (compute or previous pass done)
        if ((wn >> 1) == h) {
            #pragma unroll
            for (int mi = 0; mi < 4; mi++)
                #pragma unroll
                for (int ni = 0; ni < 2; ni++)
                    wmma::store_matrix_sync(
                        sf + (wm * 64 + mi * 16) * 68 + (wn & 1) * 32 + ni * 16,
                        cfrag[mi][ni], 68, wmma::mem_row_major);
        }
        __syncthreads();
        #pragma unroll
        for (int it = 0; it < 16; it++) {
            int idx = it * 256 + tid;         // 4096 float2 = 128 x 64
            int row = idx >> 5, c2 = (idx & 31) * 2;
            float v0 = sf[row * 68 + c2], v1 = sf[row * 68 + c2 + 1];
            int grow = bm + row;
            int gcol = bn + h * 64 + c2;
            if (MODE == 0) {
                v0 += g_pbias[gcol]; v1 += g_pbias[gcol + 1];
                int mat = gcol >> 9, col = gcol & 511;
                float* dst = (mat == 0) ? g_Q : (mat == 1) ? g_K : g_V;
                *(float2*)(dst + (size_t)grow * 512 + col) = make_float2(v0, v1);
            } else if (MODE == 1) {
                *(float2*)(g_Hk + (size_t)grow * 512 + gcol) = make_float2(v0, v1);
            } else if (MODE == 2) {
                v0 += bias[gcol]; v1 += bias[gcol + 1];
                v0 = 0.5f * v0 * (1.0f + erff(v0 * 0.7071067811865476f));
                v1 = 0.5f * v1 * (1.0f + erff(v1 * 0.7071067811865476f));
                *(float2*)(g_T1 + (size_t)grow * 512 + gcol) = make_float2(v0, v1);
            } else if (MODE == 3) {
                float2 vv = *(const float2*)(g_V + (size_t)grow * 512 + gcol);
                float s = g_attnc[grow];
                v0 += bias[gcol] + s * vv.x;
                v1 += bias[gcol + 1] + s * vv.y;
                *(float2*)(g_T2 + (size_t)grow * 512 + gcol) = make_float2(v0, v1);
            } else {
                v0 += bias[gcol]; v1 += bias[gcol + 1];
                *(float2*)(Cext + (size_t)grow * 512 + gcol) = make_float2(v0, v1);
            }
        }
    }
}

// ---------------- coherence (closed-form spectra) + softmax ----------------
__global__ void coherence_kernel() {
    int r = blockIdx.x;
    const float* q  = g_Q  + (size_t)r * DM;
    const float* k  = g_K  + (size_t)r * DM;
    const float* hk = g_Hk + (size_t)r * DM;
    float qk = 0, qq = 0, kk = 0, se_q = 0, so_q = 0, se_k = 0, so_k = 0, qh = 0;
    for (int h = threadIdx.x; h < DM; h += 128) {
        float qv = q[h], kv = k[h];
        qk += qv * kv; qq += qv * qv; kk += kv * kv; qh += qv * hk[h];
        if (h & 1) { so_q += qv; so_k += kv; }
        else       { se_q += qv; se_k += kv; }
    }
    __shared__ float sred[8][4];
    float vals[8] = {qk, qq, kk, se_q, so_q, se_k, so_k, qh};
    int lane = threadIdx.x & 31, wid = threadIdx.x >> 5;
    #pragma unroll
    for (int i = 0; i < 8; i++) {
        float v = vals[i];
        #pragma unroll
        for (int o = 16; o > 0; o >>= 1) v += __shfl_down_sync(0xffffffffu, v, o);
        if (lane == 0) sred[i][wid] = v;
    }
    __syncthreads();
    if (threadIdx.x == 0) {
        float s[8];
        #pragma unroll
        for (int i = 0; i < 8; i++) s[i] = sred[i][0] + sred[i][1] + sred[i][2] + sred[i][3];
        float a   = 256.0f * s[0] + s[3] * s[5] + s[4] * s[6];
        float b   = s[7];
        float pxx = 256.0f * s[1] + s[3] * s[3] + s[4] * s[4];
        float pyy = 256.0f * s[2] + s[5] * s[5] + s[6] * s[6];
        float coh = (a * a + b * b) / fmaxf(pxx * pyy, 66049.0f * 1e-6f);
        g_coh[r] = coh * 5.656854249492381f;   // * sqrt(D_K)
    }
}
__global__ void softmax_kernel() {
    int gidx = blockIdx.x;
    const float* x = g_coh + (size_t)gidx * 512;
    __shared__ float red[512];
    int t = threadIdx.x;
    float v = x[t];
    red[t] = v; __syncthreads();
    for (int s = 256; s > 0; s >>= 1) { if (t < s) red[t] = fmaxf(red[t], red[t + s]); __syncthreads(); }
    float mx = red[0]; __syncthreads();
    float e = expf(v - mx);
    red[t] = e; __syncthreads();
    for (int s = 256; s > 0; s >>= 1) { if (t < s) red[t] += red[t + s]; __syncthreads(); }
    g_attnc[(size_t)gidx * 512 + t] = e * (g_trace / red[0]);
}

// ---------------- launch ----------------
extern "C" void kernel_launch(void* const* d_in, const int* in_sizes, int n_in,
                              void* d_out, int out_size) {
    const float* coeffs   = (const float*)d_in[0];
    const float* proj_w   = (const float*)d_in[1];
    const float* proj_b   = (const float*)d_in[2];
    const float* var_attn = (const float*)d_in[3];
    const float* mlp1_w   = (const float*)d_in[4];
    const float* mlp1_b   = (const float*)d_in[5];
    const float* mlp2_w   = (const float*)d_in[6];
    const float* mlp2_b   = (const float*)d_in[7];
    const float* out_w    = (const float*)d_in[8];
    const float* out_b    = (const float*)d_in[9];
    float* out = (float*)d_out;
    (void)in_sizes; (void)n_in; (void)out_size;

    prep_mi  <<<512, 256>>>();
    prep_proj<<<1536, 256>>>(proj_w, proj_b);
    prep_w512<<<512, 256>>>(mlp1_w, M1_OFF);
    prep_w512<<<512, 256>>>(mlp2_w, M2_OFF);
    prep_w512<<<512, 256>>>(out_w,  OW_OFF);
    trace_kernel<<<512, 128>>>(var_attn);

    gemm_wmma<0><<<dim3(12, 512), 256>>>(coeffs, nullptr, nullptr);
    gemm_wmma<1><<<dim3(4, 512),  256>>>(nullptr, nullptr, nullptr);
    coherence_kernel<<<R_TOT, 128>>>();
    softmax_kernel<<<128, 512>>>();
    gemm_wmma<2><<<dim3(4, 512),  256>>>(nullptr, mlp1_b, nullptr);
    gemm_wmma<3><<<dim3(4, 512),  256>>>(nullptr, mlp2_b, nullptr);
    gemm_wmma<4><<<dim3(4, 512),  256>>>(nullptr, out_b, out);
}